// round 14
// baseline (speedup 1.0000x reference)
#include <cuda_runtime.h>
#include <cuda_fp16.h>
#include <cstdint>

#define DEV_INLINE __device__ __forceinline__

// ---------------- problem sizes ----------------
static constexpr int kB = 16384;
static constexpr int kD = 1024;
static constexpr int kU = 128;

// ---------------- base kernel tiling (128-row CTA, proven R11 shape) ----------------
static constexpr int B_DC  = 64;
static constexpr int B_NCH = kD / B_DC;          // 16
static constexpr int B_AREG = 128 * 128;         // 16384
static constexpr int B_BUF  = 2 * B_AREG;        // 32768
static constexpr int B_SMEM = 2 * B_BUF;         // 65536
static constexpr int B_W_U4 = B_AREG / 16;       // 1024

// ---------------- spline kernel tiling (64-row CTA, 2 CTAs/SM) ----------------
static constexpr int S_DC   = 16;
static constexpr int S_NCH  = kD / S_DC;         // 64
static constexpr int S_ROWS = 64;
// buffer layout (30720 B): A_quad 8K | A_solo 2K | W_quad 16K | W_solo 4K
static constexpr int S_AQ = 0;
static constexpr int S_AS = 8192;
static constexpr int S_WQ = 10240;
static constexpr int S_BUFB = 30720;
static constexpr int S_SMEM = 2 * S_BUFB;        // 61440
static constexpr int S_WCHUNK = 20480;           // W bytes per chunk (quad 16K + solo 4K)

// packed weights
__device__ __half g_WbPack[16 * 8192];                 // base
__device__ __half g_WsPack2[(size_t)S_NCH * (S_WCHUNK / 2)];  // spline, 655360 halves

// ---------------- PTX helpers ----------------
DEV_INLINE uint32_t smem_u32(const void* p) {
    uint32_t a;
    asm("{ .reg .u64 t; cvta.to.shared.u64 t, %1; cvt.u32.u64 %0, t; }" : "=r"(a) : "l"(p));
    return a;
}

#define LDSM_X4(r, addr)                                                        \
    asm volatile("ldmatrix.sync.aligned.m8n8.x4.shared.b16 {%0,%1,%2,%3}, [%4];"\
                 : "=r"((r)[0]), "=r"((r)[1]), "=r"((r)[2]), "=r"((r)[3])       \
                 : "r"(addr))

DEV_INLINE void mma16816(float* d, const uint32_t* a, uint32_t b0, uint32_t b1) {
    asm volatile(
        "mma.sync.aligned.m16n8k16.row.col.f32.f16.f16.f32 "
        "{%0,%1,%2,%3}, {%4,%5,%6,%7}, {%8,%9}, {%0,%1,%2,%3};"
        : "+f"(d[0]), "+f"(d[1]), "+f"(d[2]), "+f"(d[3])
        : "r"(a[0]), "r"(a[1]), "r"(a[2]), "r"(a[3]), "r"(b0), "r"(b1));
}

DEV_INLINE void cp_async16(uint32_t smem_dst, const void* gsrc) {
    asm volatile("cp.async.cg.shared.global [%0], [%1], 16;"
                 :: "r"(smem_dst), "l"(gsrc) : "memory");
}
DEV_INLINE void cp_async_commit() { asm volatile("cp.async.commit_group;" ::: "memory"); }
DEV_INLINE void cp_async_wait_all() { asm volatile("cp.async.wait_group 0;" ::: "memory"); }

// ---------------- weight prep ----------------
__global__ void kan_prep_weights(const float* __restrict__ bw,
                                 const float* __restrict__ sw) {
    int idx = blockIdx.x * blockDim.x + threadIdx.x;
    if (idx < 131072) {
        // base: [c16][n128][k64] SW128
        int k = idx & 63, n = (idx >> 6) & 127, c = idx >> 13;
        int i = c * 64 + k;
        unsigned off = (unsigned)(n * 128 + k * 2);
        unsigned swz = off ^ ((off >> 3) & 0x70);
        g_WbPack[(size_t)c * 8192 + (swz >> 1)] = __float2half(bw[i * kU + n]);
    } else {
        // spline: 64 chunks x 5 streams x 128 n x 16 k
        int j   = idx - 131072;              // 0..655359
        int c   = j / 10240;
        int rem = j - c * 10240;
        int g   = rem >> 11;                 // stream 0..4
        int r2  = rem & 2047;
        int n   = r2 >> 4;
        int k   = r2 & 15;
        int i   = c * S_DC + k;
        float v = sw[(size_t)(i * kU + n) * 8 + g];
        unsigned addr;
        if (g < 4) {
            unsigned off = (unsigned)(n * 128 + g * 32 + k * 2);
            addr = off ^ ((off >> 3) & 0x70);             // quad, SW128
        } else {
            unsigned off = (unsigned)(n * 32 + k * 2);
            addr = 16384u + (off ^ ((off >> 3) & 0x10));  // solo, 32B pitch
        }
        g_WsPack2[(size_t)c * (S_WCHUNK / 2) + (addr >> 1)] = __float2half(v);
    }
}

// =======================================================================
// BASE kernel (R11-proven): out = SiLU(x @ Wb). 4 prod + 8 cons warps.
// =======================================================================
#define BLD(OFF, J, FA, FB) do {                                                \
    LDSM_X4(&(FB)[0],  bAddr[2 * (J) + 0] + (OFF));                             \
    LDSM_X4(&(FB)[4],  bAddr[2 * (J) + 1] + (OFF));                             \
    LDSM_X4(&(FA)[0],  aAddr[0][J] + (OFF));                                    \
    LDSM_X4(&(FA)[4],  aAddr[1][J] + (OFF));                                    \
    LDSM_X4(&(FA)[8],  aAddr[2][J] + (OFF));                                    \
    LDSM_X4(&(FA)[12], aAddr[3][J] + (OFF));                                    \
} while (0)

#define BMMA(FA, FB) do {                                                       \
    _Pragma("unroll")                                                           \
    for (int mb_ = 0; mb_ < 4; ++mb_)                                           \
        _Pragma("unroll")                                                       \
        for (int nb_ = 0; nb_ < 4; ++nb_)                                       \
            mma16816(acc[mb_][nb_], &(FA)[mb_ * 4], (FB)[nb_], (FB)[4 + nb_]);  \
} while (0)

__global__ void __launch_bounds__(384, 1)
kan_base_kernel(const float* __restrict__ x, float* __restrict__ out) {
    extern __shared__ char smem[];
    const uint32_t smem_base = smem_u32(smem);
    const int tid  = threadIdx.x;
    const int wid  = tid >> 5;
    const int lane = tid & 31;
    const int row_base = blockIdx.x * 128;

    if (wid < 4) {
        const int pr = tid;
        const float* xp = x + (size_t)(row_base + pr) * kD;
        const unsigned rowOff = (unsigned)(pr * 128);
        const unsigned rXor   = (unsigned)((pr & 7) << 4);

        float4 xq[16];
        auto loadX = [&](int c) {
            const float* p = xp + c * B_DC;
            #pragma unroll
            for (int j = 0; j < 16; ++j)
                xq[j] = *reinterpret_cast<const float4*>(p + j * 4);
        };
        auto produce = [&](uint32_t bufOff) {
            #pragma unroll
            for (int g = 0; g < 8; ++g) {
                union { __half2 h2[4]; uint4 u4; } st;
                st.h2[0] = __floats2half2_rn(xq[2*g].x,   xq[2*g].y);
                st.h2[1] = __floats2half2_rn(xq[2*g].z,   xq[2*g].w);
                st.h2[2] = __floats2half2_rn(xq[2*g+1].x, xq[2*g+1].y);
                st.h2[3] = __floats2half2_rn(xq[2*g+1].z, xq[2*g+1].w);
                unsigned off = rowOff + (unsigned)(g * 16);
                unsigned swz = off ^ rXor;
                *reinterpret_cast<uint4*>(smem + bufOff + swz) = st.u4;
            }
        };
        auto copyW = [&](int c, uint32_t bufOff) {
            const char* src = reinterpret_cast<const char*>(g_WbPack) + (size_t)c * 16384;
            #pragma unroll
            for (int j = 0; j < B_W_U4 / 128; ++j) {
                int i = pr + j * 128;
                cp_async16(smem_base + bufOff + B_AREG + i * 16, src + i * 16);
            }
            cp_async_commit();
        };

        copyW(0, 0);
        loadX(0);
        produce(0);
        cp_async_wait_all();
        __syncthreads();

        for (int c = 0; c < B_NCH; ++c) {
            if (c + 1 < B_NCH) {
                uint32_t bo = (uint32_t)(((c + 1) & 1) * B_BUF);
                copyW(c + 1, bo);
                loadX(c + 1);
                produce(bo);
                cp_async_wait_all();
            }
            __syncthreads();
        }
    } else {
        const int w  = wid - 4;
        const int mi = w & 1;
        const int ni = w >> 1;

        float acc[4][4][4];
        #pragma unroll
        for (int a = 0; a < 4; ++a)
            #pragma unroll
            for (int b = 0; b < 4; ++b)
                #pragma unroll
                for (int j = 0; j < 4; ++j) acc[a][b][j] = 0.f;

        const int aRowLocal  = (lane & 7) + ((lane >> 3) & 1) * 8;
        const uint32_t kbAhi = ((lane >> 4) & 1) * 16;
        uint32_t aAddr[4][4];
        #pragma unroll
        for (int mb = 0; mb < 4; ++mb) {
            int r = mi * 64 + mb * 16 + aRowLocal;
            uint32_t base = smem_base + (uint32_t)(r * 128);
            uint32_t ax   = (uint32_t)((r & 7) << 4);
            #pragma unroll
            for (int j = 0; j < 4; ++j)
                aAddr[mb][j] = base + (((uint32_t)(j * 32) + kbAhi) ^ ax);
        }
        uint32_t bAddr[8];
        {
            int rB = ni * 32 + lane;
            uint32_t base = smem_base + (uint32_t)B_AREG + (uint32_t)(rB * 128);
            uint32_t bx   = (uint32_t)((rB & 7) << 4);
            #pragma unroll
            for (int jb = 0; jb < 8; ++jb)
                bAddr[jb] = base + (((uint32_t)(jb * 16)) ^ bx);
        }

        __syncthreads();

        uint32_t fa0[16], fa1[16], fb0[8], fb1[8];
        for (int c = 0; c < B_NCH; ++c) {
            const uint32_t bo = (uint32_t)((c & 1) * B_BUF);
            BLD(bo, 0, fa0, fb0);
            BLD(bo, 1, fa1, fb1);  BMMA(fa0, fb0);
            BLD(bo, 2, fa0, fb0);  BMMA(fa1, fb1);
            BLD(bo, 3, fa1, fb1);  BMMA(fa0, fb0);
                                   BMMA(fa1, fb1);
            __syncthreads();
        }

        const int colBase = ni * 32 + (lane & 3) * 2;
        #pragma unroll
        for (int mb = 0; mb < 4; ++mb) {
            int row0 = row_base + mi * 64 + mb * 16 + (lane >> 2);
            #pragma unroll
            for (int nb = 0; nb < 4; ++nb) {
                int col = colBase + nb * 8;
                float z0 = acc[mb][nb][0], z1 = acc[mb][nb][1];
                float z2 = acc[mb][nb][2], z3 = acc[mb][nb][3];
                float2 v0, v1;
                v0.x = __fdividef(z0, 1.f + __expf(-z0));
                v0.y = __fdividef(z1, 1.f + __expf(-z1));
                v1.x = __fdividef(z2, 1.f + __expf(-z2));
                v1.y = __fdividef(z3, 1.f + __expf(-z3));
                *reinterpret_cast<float2*>(out + (size_t)row0 * kU + col)       = v0;
                *reinterpret_cast<float2*>(out + (size_t)(row0 + 8) * kU + col) = v1;
            }
        }
    }
}

// =======================================================================
// SPLINE kernel: out += rbf-einsum. 64-row CTAs, grid 256, 2 CTAs/SM.
// 6 warps: wid 0-1 producers, wid 2-5 consumers (32x64 tiles).
// =======================================================================
#define SLDQ(J, FA, FB) do {                                                    \
    LDSM_X4(&(FB)[0],  wqB + bOff0 + (((uint32_t)((J) * 32 + 0))  ^ bXor0) + CO);\
    LDSM_X4(&(FB)[4],  wqB + bOff0 + (((uint32_t)((J) * 32 + 16)) ^ bXor0) + CO);\
    LDSM_X4(&(FB)[8],  wqB + bOff1 + (((uint32_t)((J) * 32 + 0))  ^ bXor1) + CO);\
    LDSM_X4(&(FB)[12], wqB + bOff1 + (((uint32_t)((J) * 32 + 16)) ^ bXor1) + CO);\
    LDSM_X4(&(FA)[0],  aq[0][J] + CO);                                          \
    LDSM_X4(&(FA)[4],  aq[1][J] + CO);                                          \
} while (0)

#define SLDS(FA, FB) do {                                                       \
    LDSM_X4(&(FB)[0],  bs00 + CO);                                              \
    LDSM_X4(&(FB)[4],  bs01 + CO);                                              \
    LDSM_X4(&(FB)[8],  bs10 + CO);                                              \
    LDSM_X4(&(FB)[12], bs11 + CO);                                              \
    LDSM_X4(&(FA)[0],  as0 + CO);                                               \
    LDSM_X4(&(FA)[4],  as1 + CO);                                               \
} while (0)

#define SMMA(FA, FB) do {                                                       \
    _Pragma("unroll")                                                           \
    for (int mb_ = 0; mb_ < 2; ++mb_)                                           \
        _Pragma("unroll")                                                       \
        for (int bh_ = 0; bh_ < 2; ++bh_)                                       \
            _Pragma("unroll")                                                   \
            for (int nbi_ = 0; nbi_ < 4; ++nbi_)                                \
                mma16816(acc[mb_][bh_ * 4 + nbi_], &(FA)[mb_ * 4],              \
                         (FB)[bh_ * 8 + nbi_], (FB)[bh_ * 8 + 4 + nbi_]);       \
} while (0)

__global__ void __launch_bounds__(192, 2)
kan_spline_kernel(const float* __restrict__ x, float* __restrict__ out) {
    extern __shared__ char smem[];
    const uint32_t smem_base = smem_u32(smem);
    const int tid  = threadIdx.x;
    const int wid  = tid >> 5;
    const int lane = tid & 31;
    const int row_base = blockIdx.x * S_ROWS;

    const float E375p = 42.52108200006278f;    // e^{3.75}
    const float E125p = 3.4903429574597902f;   // e^{1.25}
    const float E125m = 0.2865047968601901f;   // e^{-1.25}
    const float E375m = 0.023517745856009107f; // e^{-3.75}

    if (wid < 2) {
        // ---- producers: 64 threads, 1 row each ----
        const int pr = tid;                       // 0..63
        const float* xp = x + (size_t)(row_base + pr) * kD;

        float4 xq[4];
        auto loadX = [&](int c) {
            const float* p = xp + c * S_DC;
            #pragma unroll
            for (int j = 0; j < 4; ++j)
                xq[j] = *reinterpret_cast<const float4*>(p + j * 4);
        };
        auto produce = [&](uint32_t bufOff) {
            union { __half2 h2[8]; uint4 u4[2]; } st[5];
            #pragma unroll
            for (int q = 0; q < 4; ++q) {
                float xs0, xs1;
                #pragma unroll
                for (int h = 0; h < 2; ++h) {
                    if (h == 0) { xs0 = xq[q].x; xs1 = xq[q].y; }
                    else        { xs0 = xq[q].z; xs1 = xq[q].w; }
                    float a0 = xs0 + 1.f, a1 = xs1 + 1.f;
                    float y0a = __expf(-5.f * a0 * a0);
                    float y0b = __expf(-5.f * a1 * a1);
                    float ta  = __expf(5.f * xs0);
                    float tb  = __expf(5.f * xs1);
                    float y1a = y0a * ta * E375p, y1b = y0b * tb * E375p;
                    float y2a = y1a * ta * E125p, y2b = y1b * tb * E125p;
                    float y3a = y2a * ta * E125m, y3b = y2b * tb * E125m;
                    float y4a = y3a * ta * E375m, y4b = y3b * tb * E375m;
                    int j = q * 2 + h;
                    st[0].h2[j] = __floats2half2_rn(y0a, y0b);
                    st[1].h2[j] = __floats2half2_rn(y1a, y1b);
                    st[2].h2[j] = __floats2half2_rn(y2a, y2b);
                    st[3].h2[j] = __floats2half2_rn(y3a, y3b);
                    st[4].h2[j] = __floats2half2_rn(y4a, y4b);
                }
            }
            // quad streams 0..3
            #pragma unroll
            for (int g = 0; g < 4; ++g) {
                #pragma unroll
                for (int jj = 0; jj < 2; ++jj) {
                    unsigned off = (unsigned)(pr * 128 + g * 32 + jj * 16);
                    unsigned swz = off ^ ((off >> 3) & 0x70);
                    *reinterpret_cast<uint4*>(smem + bufOff + S_AQ + swz) = st[g].u4[jj];
                }
            }
            // solo stream 4 (32B pitch)
            #pragma unroll
            for (int jj = 0; jj < 2; ++jj) {
                unsigned off = (unsigned)(pr * 32 + jj * 16);
                unsigned swz = off ^ ((off >> 3) & 0x10);
                *reinterpret_cast<uint4*>(smem + bufOff + S_AS + swz) = st[4].u4[jj];
            }
        };
        auto copyW = [&](int c, uint32_t bufOff) {
            const char* src = reinterpret_cast<const char*>(g_WsPack2) +
                              (size_t)c * S_WCHUNK;
            #pragma unroll
            for (int j = 0; j < (S_WCHUNK / 16) / 64; ++j) {  // 20 per thread
                int i = pr + j * 64;
                cp_async16(smem_base + bufOff + S_WQ + i * 16, src + i * 16);
            }
            cp_async_commit();
        };

        // prologue: chunk 0 -> buffer 0
        loadX(0);
        copyW(0, 0);
        produce(0);
        loadX(1);
        cp_async_wait_all();
        __syncthreads();

        for (int c = 0; c < S_NCH; ++c) {
            if (c + 1 < S_NCH) {
                uint32_t bo = (uint32_t)(((c + 1) & 1) * S_BUFB);
                copyW(c + 1, bo);
                produce(bo);          // uses xq = x(c+1), loaded last iteration
                if (c + 2 < S_NCH) loadX(c + 2);
                cp_async_wait_all();
            }
            __syncthreads();
        }
    } else {
        // ---- consumers: 4 warps, 32x64 tiles ----
        const int w  = wid - 2;       // 0..3
        const int mi = w & 1;         // rows mi*32
        const int ni = w >> 1;        // cols ni*64

        float acc[2][8][4];
        #pragma unroll
        for (int a = 0; a < 2; ++a)
            #pragma unroll
            for (int b = 0; b < 8; ++b)
                #pragma unroll
                for (int j = 0; j < 4; ++j) acc[a][b][j] = 0.f;

        const int aRowLocal  = (lane & 7) + ((lane >> 3) & 1) * 8;
        const uint32_t kbAhi = ((lane >> 4) & 1) * 16;

        uint32_t aq[2][4], as0, as1;
        #pragma unroll
        for (int mb = 0; mb < 2; ++mb) {
            int r = mi * 32 + mb * 16 + aRowLocal;
            uint32_t qb = smem_base + (uint32_t)S_AQ + (uint32_t)(r * 128);
            uint32_t ax = (uint32_t)((r & 7) << 4);
            #pragma unroll
            for (int j = 0; j < 4; ++j)
                aq[mb][j] = qb + (((uint32_t)(j * 32) + kbAhi) ^ ax);
            uint32_t sb = smem_base + (uint32_t)S_AS + (uint32_t)(r * 32);
            uint32_t sx = (uint32_t)(((r >> 2) & 1) << 4);
            if (mb == 0) as0 = sb + (kbAhi ^ sx); else as1 = sb + (kbAhi ^ sx);
        }
        const uint32_t wqB = smem_base + (uint32_t)S_WQ;
        const int rn0 = ni * 64 + lane;
        const int rn1 = ni * 64 + 32 + lane;
        const uint32_t bOff0 = (uint32_t)(rn0 * 128);
        const uint32_t bXor0 = (uint32_t)((rn0 & 7) << 4);
        const uint32_t bOff1 = (uint32_t)(rn1 * 128);
        const uint32_t bXor1 = (uint32_t)((rn1 & 7) << 4);
        uint32_t bs00, bs01, bs10, bs11;
        {
            uint32_t wsB = smem_base + (uint32_t)(S_WQ + 16384);
            uint32_t x0 = (uint32_t)(((rn0 >> 2) & 1) << 4);
            uint32_t x1 = (uint32_t)(((rn1 >> 2) & 1) << 4);
            bs00 = wsB + (uint32_t)(rn0 * 32) + (0u  ^ x0);
            bs01 = wsB + (uint32_t)(rn0 * 32) + (16u ^ x0);
            bs10 = wsB + (uint32_t)(rn1 * 32) + (0u  ^ x1);
            bs11 = wsB + (uint32_t)(rn1 * 32) + (16u ^ x1);
        }

        __syncthreads();   // matches producer prologue sync

        uint32_t fa0[8], fa1[8], fb0[16], fb1[16];
        for (int c = 0; c < S_NCH; ++c) {
            const uint32_t CO = (uint32_t)((c & 1) * S_BUFB);
            SLDQ(0, fa0, fb0);
            SLDQ(1, fa1, fb1);  SMMA(fa0, fb0);
            SLDQ(2, fa0, fb0);  SMMA(fa1, fb1);
            SLDQ(3, fa1, fb1);  SMMA(fa0, fb0);
            SLDS(fa0, fb0);     SMMA(fa1, fb1);
                                SMMA(fa0, fb0);
            __syncthreads();
        }

        // epilogue: out += spline (out holds SiLU(base) from base kernel)
        const int colBase = ni * 64 + (lane & 3) * 2;
        #pragma unroll
        for (int mb = 0; mb < 2; ++mb) {
            int row0 = row_base + mi * 32 + mb * 16 + (lane >> 2);
            #pragma unroll
            for (int nb = 0; nb < 8; ++nb) {
                int col = colBase + (nb >> 2) * 32 + (nb & 3) * 8;
                float2* p0 = reinterpret_cast<float2*>(out + (size_t)row0 * kU + col);
                float2* p1 = reinterpret_cast<float2*>(out + (size_t)(row0 + 8) * kU + col);
                float2 v0 = *p0, v1 = *p1;
                v0.x += acc[mb][nb][0]; v0.y += acc[mb][nb][1];
                v1.x += acc[mb][nb][2]; v1.y += acc[mb][nb][3];
                *p0 = v0; *p1 = v1;
            }
        }
    }
}

// ---------------- launch ----------------
extern "C" void kernel_launch(void* const* d_in, const int* in_sizes, int n_in,
                              void* d_out, int out_size) {
    (void)in_sizes; (void)n_in; (void)out_size;
    const float* x  = (const float*)d_in[0];
    const float* bw = (const float*)d_in[1];
    const float* sw = (const float*)d_in[2];
    float* out = (float*)d_out;

    cudaFuncSetAttribute(kan_base_kernel,
                         cudaFuncAttributeMaxDynamicSharedMemorySize, B_SMEM);
    cudaFuncSetAttribute(kan_spline_kernel,
                         cudaFuncAttributeMaxDynamicSharedMemorySize, S_SMEM);

    kan_prep_weights<<<(131072 + 655360) / 256, 256>>>(bw, sw);
    kan_base_kernel<<<kB / 128, 384, B_SMEM>>>(x, out);
    kan_spline_kernel<<<kB / S_ROWS, 192, S_SMEM>>>(x, out);
}

// round 15
// speedup vs baseline: 1.2306x; 1.2306x over previous
#include <cuda_runtime.h>
#include <cuda_fp16.h>
#include <cstdint>

#define DEV_INLINE __device__ __forceinline__

// ---------------- problem sizes ----------------
static constexpr int kB = 16384;
static constexpr int kD = 1024;
static constexpr int kU = 128;

// ---------------- tiling (R5 champion topology) ----------------
static constexpr int DC    = 32;            // K per chunk
static constexpr int NCH   = kD / DC;       // 32 chunks
static constexpr int PAIRS = 3;             // stream pairs (0,1),(2,3),(4,5)
static constexpr int PAIR_BYTES = 128 * 128;           // 128 rows x 128B
static constexpr int HALF_BUF   = PAIRS * PAIR_BYTES;  // 49152 (A region or W region)
static constexpr int BUF_BYTES  = 2 * HALF_BUF;        // 98304 per buffer
static constexpr int SMEM_TOTAL = 2 * BUF_BYTES;       // 196608 double-buffered

static constexpr int W_HALVES = NCH * PAIRS * 8192;    // 786432 fp16
static constexpr int W_U4_PER_CHUNK = PAIRS * 8192 * 2 / 16;  // 3072 uint4

static constexpr int NTHREADS = 384;        // 8 consumer warps (0-7) + 4 producer warps (8-11)

// prepacked, SW128-swizzled fp16 weights: [chunk32][pair][128 rows][128B (2 streams)]
__device__ __half g_Wpack[W_HALVES];

// ---------------- PTX helpers ----------------
DEV_INLINE uint32_t smem_u32(const void* p) {
    uint32_t a;
    asm("{ .reg .u64 t; cvta.to.shared.u64 t, %1; cvt.u32.u64 %0, t; }" : "=r"(a) : "l"(p));
    return a;
}

#define LDSM_X4(r, addr)                                                        \
    asm volatile("ldmatrix.sync.aligned.m8n8.x4.shared.b16 {%0,%1,%2,%3}, [%4];"\
                 : "=r"((r)[0]), "=r"((r)[1]), "=r"((r)[2]), "=r"((r)[3])       \
                 : "r"(addr))

DEV_INLINE void mma16816(float* d, const uint32_t* a, uint32_t b0, uint32_t b1) {
    asm volatile(
        "mma.sync.aligned.m16n8k16.row.col.f32.f16.f16.f32 "
        "{%0,%1,%2,%3}, {%4,%5,%6,%7}, {%8,%9}, {%0,%1,%2,%3};"
        : "+f"(d[0]), "+f"(d[1]), "+f"(d[2]), "+f"(d[3])
        : "r"(a[0]), "r"(a[1]), "r"(a[2]), "r"(a[3]), "r"(b0), "r"(b1));
}

DEV_INLINE void cp_async16(uint32_t smem_dst, const void* gsrc) {
    asm volatile("cp.async.cg.shared.global [%0], [%1], 16;"
                 :: "r"(smem_dst), "l"(gsrc) : "memory");
}
DEV_INLINE void cp_async_commit() { asm volatile("cp.async.commit_group;" ::: "memory"); }
DEV_INLINE void cp_async_wait_all() { asm volatile("cp.async.wait_group 0;" ::: "memory"); }

// ---------------- weight prep: vectorized (one uint4 store per thread) ----------------
// Each thread packs 8 consecutive k-halves of one (chunk, pair, n, slo) row group.
// The SW128 swizzle XORs only bits [4:6], so a 16B-aligned group maps to one
// 16B-aligned target -> single STG.128.
__global__ void kan_prep_weights(const float* __restrict__ bw,
                                 const float* __restrict__ sw) {
    int u = blockIdx.x * blockDim.x + threadIdx.x;   // 0..98303
    if (u >= W_HALVES / 8) return;
    int g16 = u & 7;               // which 16B group within the 128B row
    int n   = (u >> 3) & 127;      // output unit
    int t3  = u >> 10;             // c*3 + p
    int p   = t3 % 3;
    int c   = t3 / 3;
    int slo = g16 >> 2;            // stream half (0/1)
    int k0  = (g16 & 3) * 8;       // first k of this group
    int s   = p * 2 + slo;         // stream 0..5 (0 = base weights)

    __half h[8];
    #pragma unroll
    for (int j = 0; j < 8; ++j) {
        int i = c * DC + k0 + j;
        float v = (s == 0) ? bw[i * kU + n]
                           : sw[(size_t)(i * kU + n) * 8 + (s - 1)];
        h[j] = __float2half(v);
    }
    unsigned off = (unsigned)(n * 128 + slo * 64 + k0 * 2);   // 16B aligned
    unsigned swz = off ^ ((off >> 3) & 0x70);
    *reinterpret_cast<uint4*>(reinterpret_cast<char*>(g_Wpack) +
                              (size_t)t3 * 16384 + swz) =
        *reinterpret_cast<const uint4*>(h);
}

// ---------------- main fused kernel (R5 topology + micro-tweaks) ----------------
__global__ void __launch_bounds__(NTHREADS, 1)
kan_main_kernel(const float* __restrict__ x, float* __restrict__ out) {
    extern __shared__ char smem[];
    const uint32_t smem_base = smem_u32(smem);
    const int tid  = threadIdx.x;
    const int wid  = tid >> 5;
    const int lane = tid & 31;
    const int row_base = blockIdx.x * 128;

    // rbf chain constants
    const float E375p = 42.52108200006278f;    // e^{3.75}
    const float E125p = 3.4903429574597902f;   // e^{1.25}
    const float E125m = 0.2865047968601901f;   // e^{-1.25}
    const float E375m = 0.023517745856009107f; // e^{-3.75}

    if (wid >= 8) {
        // ============ PRODUCER warps (4 warps = 128 threads, 1 row each) ============
        const int pr = tid - 256;                  // 0..127
        const float* xp = x + (size_t)(row_base + pr) * kD;
        const uint32_t aSw = (uint32_t)((pr & 7) << 4);

        float4 xq[8];                              // one chunk of x, prefetched
        auto loadX = [&](int c) {
            const float* xc = xp + c * DC;
            #pragma unroll
            for (int j = 0; j < 8; ++j)
                xq[j] = *reinterpret_cast<const float4*>(xc + j * 4);
        };

        auto produce = [&](uint32_t aRegionOff) {  // consumes current xq
            #pragma unroll
            for (int g = 0; g < 4; ++g) {
                float xs[8];
                xs[0]=xq[2*g].x;   xs[1]=xq[2*g].y;   xs[2]=xq[2*g].z;   xs[3]=xq[2*g].w;
                xs[4]=xq[2*g+1].x; xs[5]=xq[2*g+1].y; xs[6]=xq[2*g+1].z; xs[7]=xq[2*g+1].w;
                union { __half2 h2[4]; uint4 u4; } st[6];
                #pragma unroll
                for (int e = 0; e < 8; e += 2) {
                    float a0 = xs[e] + 1.f, a1 = xs[e+1] + 1.f;
                    float y0a = __expf(-5.f * a0 * a0);
                    float y0b = __expf(-5.f * a1 * a1);
                    float ta  = __expf(5.f * xs[e]);
                    float tb  = __expf(5.f * xs[e+1]);
                    float y1a = y0a * ta * E375p, y1b = y0b * tb * E375p;
                    float y2a = y1a * ta * E125p, y2b = y1b * tb * E125p;
                    float y3a = y2a * ta * E125m, y3b = y2b * tb * E125m;
                    float y4a = y3a * ta * E375m, y4b = y3b * tb * E375m;
                    int j = e >> 1;
                    st[0].h2[j] = __floats2half2_rn(xs[e], xs[e+1]);
                    st[1].h2[j] = __floats2half2_rn(y0a, y0b);
                    st[2].h2[j] = __floats2half2_rn(y1a, y1b);
                    st[3].h2[j] = __floats2half2_rn(y2a, y2b);
                    st[4].h2[j] = __floats2half2_rn(y3a, y3b);
                    st[5].h2[j] = __floats2half2_rn(y4a, y4b);
                }
                #pragma unroll
                for (int s = 0; s < 6; ++s) {
                    int p = s >> 1, slo = s & 1;
                    unsigned off = (unsigned)(pr * 128 + slo * 64 + g * 16);
                    unsigned swz = off ^ aSw;
                    *reinterpret_cast<uint4*>(smem + aRegionOff + p * PAIR_BYTES + swz)
                        = st[s].u4;
                }
            }
        };

        auto copyW = [&](int c, uint32_t wRegion) {
            const char* src = reinterpret_cast<const char*>(g_Wpack) +
                              (size_t)c * (PAIRS * 8192 * 2);
            #pragma unroll
            for (int j = 0; j < W_U4_PER_CHUNK / 128; ++j) {  // 24 per thread
                int i = pr + j * 128;
                cp_async16(wRegion + i * 16, src + i * 16);
            }
            cp_async_commit();
        };

        // prologue: chunk 0 -> buffer 0 (and prefetch x(1))
        loadX(0);
        copyW(0, smem_base + HALF_BUF);
        produce(0);
        if (NCH > 1) loadX(1);
        cp_async_wait_all();
        __syncthreads();

        for (int c = 0; c < NCH; ++c) {
            if (c + 1 < NCH) {
                const uint32_t bufOff = (uint32_t)(((c + 1) & 1) * BUF_BYTES);
                copyW(c + 1, smem_base + bufOff + HALF_BUF);
                produce(bufOff);                  // x(c+1) already in registers
                if (c + 2 < NCH) loadX(c + 2);    // prefetch next
                cp_async_wait_all();
            }
            __syncthreads();
        }
    } else {
        // ============ CONSUMER warps (8, wid 0-7): 64x32 tiles ============
        const int mi = wid & 1;        // rows mi*64
        const int ni = wid >> 1;       // cols ni*32

        float acc0[4][4][4], acc1[4][4][4];
        #pragma unroll
        for (int a = 0; a < 4; ++a)
            #pragma unroll
            for (int b = 0; b < 4; ++b)
                #pragma unroll
                for (int j = 0; j < 4; ++j) { acc0[a][b][j] = 0.f; acc1[a][b][j] = 0.f; }

        const int aRowLocal  = (lane & 7) + ((lane >> 3) & 1) * 8;
        const uint32_t kbAhi = ((lane >> 4) & 1) * 16;
        uint32_t aOff[4], aXor[4];
        #pragma unroll
        for (int mb = 0; mb < 4; ++mb) {
            int r = mi * 64 + mb * 16 + aRowLocal;
            aOff[mb] = (uint32_t)(r * 128);
            aXor[mb] = (uint32_t)((r & 7) << 4);
        }
        const int rB = ni * 32 + lane;
        const uint32_t bOff = (uint32_t)(rB * 128);
        const uint32_t bXor = (uint32_t)((rB & 7) << 4);

        __syncthreads();  // matches producer prologue sync

        for (int c = 0; c < NCH; ++c) {
            const uint32_t bufc  = smem_base + (uint32_t)((c & 1) * BUF_BYTES);
            const uint32_t aBase = bufc;
            const uint32_t bBase = bufc + HALF_BUF;

            #pragma unroll
            for (int kk = 0; kk < 2; ++kk) {
                #pragma unroll
                for (int s = 0; s < 6; ++s) {
                    const int p = s >> 1, slo = s & 1;
                    const uint32_t pOff = (uint32_t)(p * PAIR_BYTES);
                    const uint32_t kbC  = (uint32_t)(slo * 64 + kk * 32);

                    // B first: the MMAs' earliest dependency
                    uint32_t bb[8];
                    LDSM_X4(bb,     bBase + pOff + bOff + ((kbC + 0u)  ^ bXor));
                    LDSM_X4(bb + 4, bBase + pOff + bOff + ((kbC + 16u) ^ bXor));

                    uint32_t a[16];
                    {
                        const uint32_t kbA = kbC + kbAhi;
                        #pragma unroll
                        for (int mb = 0; mb < 4; ++mb)
                            LDSM_X4(a + mb * 4,
                                    aBase + pOff + aOff[mb] + (kbA ^ aXor[mb]));
                    }

                    if (s == 0) {
                        #pragma unroll
                        for (int mb = 0; mb < 4; ++mb)
                            #pragma unroll
                            for (int nb = 0; nb < 4; ++nb)
                                mma16816(acc0[mb][nb], a + mb * 4, bb[nb], bb[4 + nb]);
                    } else {
                        #pragma unroll
                        for (int mb = 0; mb < 4; ++mb)
                            #pragma unroll
                            for (int nb = 0; nb < 4; ++nb)
                                mma16816(acc1[mb][nb], a + mb * 4, bb[nb], bb[4 + nb]);
                    }
                }
            }
            __syncthreads();
        }

        // epilogue: SiLU(base) + spline
        const int colBase = ni * 32 + (lane & 3) * 2;
        #pragma unroll
        for (int mb = 0; mb < 4; ++mb) {
            int row0 = row_base + mi * 64 + mb * 16 + (lane >> 2);
            #pragma unroll
            for (int nb = 0; nb < 4; ++nb) {
                int col = colBase + nb * 8;
                float z0 = acc0[mb][nb][0], z1 = acc0[mb][nb][1];
                float z2 = acc0[mb][nb][2], z3 = acc0[mb][nb][3];
                float2 v0, v1;
                v0.x = __fdividef(z0, 1.f + __expf(-z0)) + acc1[mb][nb][0];
                v0.y = __fdividef(z1, 1.f + __expf(-z1)) + acc1[mb][nb][1];
                v1.x = __fdividef(z2, 1.f + __expf(-z2)) + acc1[mb][nb][2];
                v1.y = __fdividef(z3, 1.f + __expf(-z3)) + acc1[mb][nb][3];
                *reinterpret_cast<float2*>(out + (size_t)row0 * kU + col)       = v0;
                *reinterpret_cast<float2*>(out + (size_t)(row0 + 8) * kU + col) = v1;
            }
        }
    }
}

// ---------------- launch ----------------
extern "C" void kernel_launch(void* const* d_in, const int* in_sizes, int n_in,
                              void* d_out, int out_size) {
    (void)in_sizes; (void)n_in; (void)out_size;
    const float* x  = (const float*)d_in[0];
    const float* bw = (const float*)d_in[1];
    const float* sw = (const float*)d_in[2];
    float* out = (float*)d_out;

    cudaFuncSetAttribute(kan_main_kernel,
                         cudaFuncAttributeMaxDynamicSharedMemorySize, SMEM_TOTAL);

    kan_prep_weights<<<(W_HALVES / 8 + 255) / 256, 256>>>(bw, sw);
    kan_main_kernel<<<kB / 128, NTHREADS, SMEM_TOTAL>>>(x, out);
}